// round 12
// baseline (speedup 1.0000x reference)
#include <cuda_runtime.h>
#include <stdint.h>
#include <math.h>

// ---------------------------------------------------------------------------
// out[b,o] = min_i ( x[b,i] + mask[o,i] ),  B=IN=OUT=512,  x in [0,1)
// mask in {0,1}  =>  out[b,o] = min over SELECTED i of x[b,i]  (sparse min).
// Selection = JAX threefry bernoulli (partitionable variant, validated R2-R11).
// One persistent kernel; per-CTA warp specialization: warps 0-3 mask (ALU),
// warps 4-7 sort (shfl/LDS) -> grid barrier -> all warps gather.
// ---------------------------------------------------------------------------

#define B_DIM   512
#define IN_DIM  512
#define OUT_DIM 512
#define NBLK    512u

// column-major selection bitmask: bit o%32 of g_selC[(o>>5)*512 + i]
__device__ uint32_t g_selC[16 * IN_DIM];
__device__ unsigned g_bar;        // monotonic epoch counter (never reset)

// ---------------- Threefry-2x32 (constexpr) --------------------------------
struct TF2 { uint32_t a, b; };

__host__ __device__ constexpr uint32_t rotl32(uint32_t v, int r) {
    return (v << r) | (v >> (32 - r));
}

__host__ __device__ constexpr TF2 tf2x32(uint32_t k0, uint32_t k1,
                                         uint32_t x0, uint32_t x1) {
    uint32_t k2 = k0 ^ k1 ^ 0x1BD11BDAu;
    x0 += k0; x1 += k1;
    x0 += x1; x1 = rotl32(x1, 13) ^ x0;
    x0 += x1; x1 = rotl32(x1, 15) ^ x0;
    x0 += x1; x1 = rotl32(x1, 26) ^ x0;
    x0 += x1; x1 = rotl32(x1,  6) ^ x0;
    x0 += k1; x1 += k2 + 1u;
    x0 += x1; x1 = rotl32(x1, 17) ^ x0;
    x0 += x1; x1 = rotl32(x1, 29) ^ x0;
    x0 += x1; x1 = rotl32(x1, 16) ^ x0;
    x0 += x1; x1 = rotl32(x1, 24) ^ x0;
    x0 += k2; x1 += k0 + 2u;
    x0 += x1; x1 = rotl32(x1, 13) ^ x0;
    x0 += x1; x1 = rotl32(x1, 15) ^ x0;
    x0 += x1; x1 = rotl32(x1, 26) ^ x0;
    x0 += x1; x1 = rotl32(x1,  6) ^ x0;
    x0 += k0; x1 += k1 + 3u;
    x0 += x1; x1 = rotl32(x1, 17) ^ x0;
    x0 += x1; x1 = rotl32(x1, 29) ^ x0;
    x0 += x1; x1 = rotl32(x1, 16) ^ x0;
    x0 += x1; x1 = rotl32(x1, 24) ^ x0;
    x0 += k1; x1 += k2 + 4u;
    x0 += x1; x1 = rotl32(x1, 13) ^ x0;
    x0 += x1; x1 = rotl32(x1, 15) ^ x0;
    x0 += x1; x1 = rotl32(x1, 26) ^ x0;
    x0 += x1; x1 = rotl32(x1,  6) ^ x0;
    x0 += k2; x1 += k0 + 5u;
    return TF2{x0, x1};
}

constexpr TF2 KB = tf2x32(0u, 42u, 0u, 0u);   // k_bern (foldlike split of key 42)

// ---------------- bernoulli decision (validated) -----------------------------
__device__ __forceinline__ bool edge_selected(const float2 w, uint32_t n) {
    TF2 r = tf2x32(KB.a, KB.b, 0u, n);
    uint32_t bits = r.a ^ r.b;
    float u = __uint_as_float((bits >> 9) | 0x3F800000u) - 1.0f;
    float t = u * (1.0f + __expf(w.x - w.y));
    if (t < 1.0f - 1e-5f) return true;
    if (t > 1.0f + 1e-5f) return false;
    double e = exp((double)w.x - (double)w.y);       // boundary: exact fp64
    return ((double)u) * (1.0 + e) < 1.0;
}

// ---------------- 4-elem/thread bitonic helpers (128 threads, e = 4*t2+c) ---
#define BSWAP(A, PA, KEEPMIN) ((KEEPMIN) ? umin((A),(PA)) : umax((A),(PA)))
#define NBAR() asm volatile("bar.sync 1, 128;" ::: "memory")

#define CE(A, B, ASC) { uint32_t lo_ = umin(A,B), hi_ = umax(A,B);            \
                        A = (ASC) ? lo_ : hi_;  B = (ASC) ? hi_ : lo_; }

// intra-thread j=2 then j=1 (uniform dir)
#define INTRA(D) { CE(v0, v2, D) CE(v1, v3, D) CE(v0, v1, D) CE(v2, v3, D) }

// shfl stage: elements j = 4*J4
#define SSTAGE(J4, D) {                                                       \
    uint32_t p0_ = __shfl_xor_sync(0xFFFFFFFFu, v0, J4);                      \
    uint32_t p1_ = __shfl_xor_sync(0xFFFFFFFFu, v1, J4);                      \
    uint32_t p2_ = __shfl_xor_sync(0xFFFFFFFFu, v2, J4);                      \
    uint32_t p3_ = __shfl_xor_sync(0xFFFFFFFFu, v3, J4);                      \
    bool km_ = (D) == ((t2 & (J4)) == 0);                                     \
    v0 = BSWAP(v0, p0_, km_); v1 = BSWAP(v1, p1_, km_);                       \
    v2 = BSWAP(v2, p2_, km_); v3 = BSWAP(v3, p3_, km_); }

// smem stage: elements j = 4*J4, J4 in {32,64} (cross-warp)
#define MSTAGE(J4, D) {                                                       \
    NBAR();                                                                   \
    reinterpret_cast<uint4*>(sk)[t2] = make_uint4(v0, v1, v2, v3);            \
    NBAR();                                                                   \
    uint4 pv_ = reinterpret_cast<uint4*>(sk)[t2 ^ (J4)];                      \
    bool km_ = (D) == ((t2 & (J4)) == 0);                                     \
    v0 = BSWAP(v0, pv_.x, km_); v1 = BSWAP(v1, pv_.y, km_);                   \
    v2 = BSWAP(v2, pv_.z, km_); v3 = BSWAP(v3, pv_.w, km_); }

// 5-step butterfly 32x32 bit-matrix transpose across lanes
#define TSTEP(V, K, M) {                                                      \
    uint32_t y_ = __shfl_xor_sync(0xFFFFFFFFu, V, K);                         \
    V = (lane & (K)) ? ((V & (M)) | ((y_ >> (K)) & ~(M)))                     \
                     : ((V & ~(M)) | ((y_ << (K)) & (M))); }

#define TRANSPOSE32(V) TSTEP(V, 16, 0xFFFF0000u) TSTEP(V, 8, 0xFF00FF00u)     \
                       TSTEP(V, 4,  0xF0F0F0F0u) TSTEP(V, 2, 0xCCCCCCCCu)     \
                       TSTEP(V, 1,  0xAAAAAAAAu)

// ---------------- fused persistent kernel -----------------------------------
__global__ __launch_bounds__(256, 4) void fused_kernel(
    const float* __restrict__ x, const float* __restrict__ pw,
    float* __restrict__ out) {
    __shared__ uint32_t sk[512];
    __shared__ float    s_xv[512];
    __shared__ uint32_t s_ti[64];
    __shared__ float    s_tv[64];
    __shared__ unsigned s_tgt;

    const int t    = threadIdx.x;
    const int bid  = blockIdx.x;
    const int lane = t & 31;

    if (t < 128) {
        // ==== warps 0-3: mask, 512 edges (ow = bid&15, i in [ib,ib+16)) =====
        const uint32_t ow = (uint32_t)bid & 15u;
        const uint32_t ib = ((uint32_t)bid >> 4) * 16u;
        const uint32_t w  = (uint32_t)t >> 5;          // 0..3
        const uint32_t o  = ow * 32u + lane;

        uint32_t ii[4]; bool s[4];
#pragma unroll
        for (int k = 0; k < 4; ++k) {
            ii[k] = ib + 4u * w + k;
            uint32_t n = o * 512u + ii[k];
            float2 wt = reinterpret_cast<const float2*>(pw)[n];
            s[k] = edge_selected(wt, n);               // 4 independent chains
        }
#pragma unroll
        for (int k = 0; k < 4; ++k) {
            uint32_t word = __ballot_sync(0xFFFFFFFFu, s[k]);
            if (lane == 0) g_selC[ow * 512u + ii[k]] = word;
        }
    } else {
        // ==== warps 4-7: 128-thread bitonic sort of x-row bid ===============
        const int t2 = t - 128;                        // 0..127, e = 4*t2+c
        float4 xv = reinterpret_cast<const float4*>(x + bid * IN_DIM)[t2];
        reinterpret_cast<float4*>(s_xv)[t2] = xv;
        uint32_t v0 = ((__float_as_uint(xv.x) >> 7) << 9) | (uint32_t)(4*t2+0);
        uint32_t v1 = ((__float_as_uint(xv.y) >> 7) << 9) | (uint32_t)(4*t2+1);
        uint32_t v2 = ((__float_as_uint(xv.z) >> 7) << 9) | (uint32_t)(4*t2+2);
        uint32_t v3 = ((__float_as_uint(xv.w) >> 7) << 9) | (uint32_t)(4*t2+3);

        // k=2: (v0,v1) asc, (v2,v3) desc
        CE(v0, v1, true) CE(v2, v3, false)
        // k=4
        { bool d = ((t2 & 1) == 0); INTRA(d) }
        // k=8
        { bool d = ((t2 & 2) == 0); SSTAGE(1, d) INTRA(d) }
        // k=16
        { bool d = ((t2 & 4) == 0); SSTAGE(2, d) SSTAGE(1, d) INTRA(d) }
        // k=32
        { bool d = ((t2 & 8) == 0); SSTAGE(4, d) SSTAGE(2, d) SSTAGE(1, d) INTRA(d) }
        // k=64
        { bool d = ((t2 & 16) == 0);
          SSTAGE(8, d) SSTAGE(4, d) SSTAGE(2, d) SSTAGE(1, d) INTRA(d) }
        // k=128
        { bool d = ((t2 & 32) == 0);
          SSTAGE(16, d) SSTAGE(8, d) SSTAGE(4, d) SSTAGE(2, d) SSTAGE(1, d) INTRA(d) }
        // k=256
        { bool d = ((t2 & 64) == 0);
          MSTAGE(32, d)
          SSTAGE(16, d) SSTAGE(8, d) SSTAGE(4, d) SSTAGE(2, d) SSTAGE(1, d) INTRA(d) }
        // k=512
        { const bool d = true;
          MSTAGE(64, d) MSTAGE(32, d)
          SSTAGE(16, d) SSTAGE(8, d) SSTAGE(4, d) SSTAGE(2, d) SSTAGE(1, d) INTRA(d) }

        if (t2 < 16) {                 // sorted elems 0..63 -> smem top list
            uint32_t i0 = v0 & 511u, i1 = v1 & 511u,
                     i2 = v2 & 511u, i3 = v3 & 511u;
            s_ti[4*t2+0] = i0;  s_tv[4*t2+0] = s_xv[i0];
            s_ti[4*t2+1] = i1;  s_tv[4*t2+1] = s_xv[i1];
            s_ti[4*t2+2] = i2;  s_tv[4*t2+2] = s_xv[i2];
            s_ti[4*t2+3] = i3;  s_tv[4*t2+3] = s_xv[i3];
        }
    }

    // ======== grid barrier (all co-resident: 512 blocks <= 148*4) ===========
    __syncthreads();
    if (t == 0) {
        __threadfence();
        unsigned arr = atomicAdd(&g_bar, 1u);
        s_tgt = (arr / NBLK + 1u) * NBLK;
    }
    __syncthreads();
    if (t == 0) {
        unsigned tgt = s_tgt, v;
        for (;;) {
            asm volatile("ld.global.acquire.gpu.u32 %0, [%1];"
                         : "=r"(v) : "l"(&g_bar));
            if (v >= tgt) break;
            __nanosleep(64);
        }
    }
    __syncthreads();

    // ======== Phase C: gather for b = bid; warp w -> ow = w and w+8 =========
    {
        const uint32_t wrp = (uint32_t)t >> 5;        // 0..7
        const uint32_t ow0 = wrp, ow1 = wrp + 8u;
        uint32_t idx = s_ti[lane];                    // candidate lane
        float    val = s_tv[lane];
        uint32_t m0 = g_selC[ow0 * 512u + idx];       // scattered, L2/L1
        uint32_t m1 = g_selC[ow1 * 512u + idx];
        TRANSPOSE32(m0)
        TRANSPOSE32(m1)
        bool ok0 = (m0 != 0), ok1 = (m1 != 0);
        float r0 = __shfl_sync(0xFFFFFFFFu, val, ok0 ? (__ffs(m0) - 1) : 0);
        float r1 = __shfl_sync(0xFFFFFFFFu, val, ok1 ? (__ffs(m1) - 1) : 0);

        if (!__all_sync(0xFFFFFFFFu, ok0 && ok1)) {   // P ~ 2.6e-3 per warp
            uint32_t idx2 = s_ti[32 + lane];
            float    val2 = s_tv[32 + lane];
            uint32_t n0 = g_selC[ow0 * 512u + idx2];
            uint32_t n1 = g_selC[ow1 * 512u + idx2];
            TRANSPOSE32(n0)
            TRANSPOSE32(n1)
            float q0 = __shfl_sync(0xFFFFFFFFu, val2, n0 ? (__ffs(n0) - 1) : 0);
            float q1 = __shfl_sync(0xFFFFFFFFu, val2, n1 ? (__ffs(n1) - 1) : 0);
            if (!ok0 && n0) { r0 = q0; ok0 = true; }
            if (!ok1 && n1) { r1 = q1; ok1 = true; }

            if (!ok0 || !ok1) {                       // P ~ 1e-9: exact dense
                float b0 = INFINITY, b1 = INFINITY, ball = INFINITY;
                for (int i = 0; i < IN_DIM; ++i) {
                    float v = s_xv[i];
                    ball = fminf(ball, v);
                    if ((g_selC[ow0 * 512u + i] >> lane) & 1u) b0 = fminf(b0, v);
                    if ((g_selC[ow1 * 512u + i] >> lane) & 1u) b1 = fminf(b1, v);
                }
                if (!ok0) r0 = isinf(b0) ? ball + 1.0f : b0;
                if (!ok1) r1 = isinf(b1) ? ball + 1.0f : b1;
            }
        }

        out[bid * OUT_DIM + ow0 * 32u + lane] = r0;   // coalesced
        out[bid * OUT_DIM + ow1 * 32u + lane] = r1;
    }
}

// ---------------------------------------------------------------------------
extern "C" void kernel_launch(void* const* d_in, const int* in_sizes, int n_in,
                              void* d_out, int out_size) {
    const float* x  = (const float*)d_in[0];   // [512, 512]
    const float* pw = (const float*)d_in[1];   // [512, 512, 2]
    float* out      = (float*)d_out;           // [512, 512]

    fused_kernel<<<NBLK, 256>>>(x, pw, out);
}

// round 13
// speedup vs baseline: 1.0269x; 1.0269x over previous
#include <cuda_runtime.h>
#include <stdint.h>
#include <math.h>

// ---------------------------------------------------------------------------
// out[b,o] = min_i ( x[b,i] + mask[o,i] ),  B=IN=OUT=512,  x in [0,1)
// mask in {0,1}  =>  out[b,o] = min over SELECTED i of x[b,i]  (sparse min).
// Selection = JAX threefry bernoulli (partitionable variant, validated R2-R12).
// One persistent kernel; warps 0-3 mask (ALU), warps 4-7 sort (shfl/LDS)
// -> grid barrier -> staged gather. All global accesses coalesced.
// ---------------------------------------------------------------------------

#define B_DIM   512
#define IN_DIM  512
#define OUT_DIM 512
#define NBLK    512u

// ROW-major selection bitmask: bit o%32 of g_sel[i*16 + (o>>5)]
__device__ uint32_t g_sel[IN_DIM * 16];
__device__ unsigned g_bar;        // monotonic epoch counter (never reset)

// ---------------- Threefry-2x32 (constexpr) --------------------------------
struct TF2 { uint32_t a, b; };

__host__ __device__ constexpr uint32_t rotl32(uint32_t v, int r) {
    return (v << r) | (v >> (32 - r));
}

__host__ __device__ constexpr TF2 tf2x32(uint32_t k0, uint32_t k1,
                                         uint32_t x0, uint32_t x1) {
    uint32_t k2 = k0 ^ k1 ^ 0x1BD11BDAu;
    x0 += k0; x1 += k1;
    x0 += x1; x1 = rotl32(x1, 13) ^ x0;
    x0 += x1; x1 = rotl32(x1, 15) ^ x0;
    x0 += x1; x1 = rotl32(x1, 26) ^ x0;
    x0 += x1; x1 = rotl32(x1,  6) ^ x0;
    x0 += k1; x1 += k2 + 1u;
    x0 += x1; x1 = rotl32(x1, 17) ^ x0;
    x0 += x1; x1 = rotl32(x1, 29) ^ x0;
    x0 += x1; x1 = rotl32(x1, 16) ^ x0;
    x0 += x1; x1 = rotl32(x1, 24) ^ x0;
    x0 += k2; x1 += k0 + 2u;
    x0 += x1; x1 = rotl32(x1, 13) ^ x0;
    x0 += x1; x1 = rotl32(x1, 15) ^ x0;
    x0 += x1; x1 = rotl32(x1, 26) ^ x0;
    x0 += x1; x1 = rotl32(x1,  6) ^ x0;
    x0 += k0; x1 += k1 + 3u;
    x0 += x1; x1 = rotl32(x1, 17) ^ x0;
    x0 += x1; x1 = rotl32(x1, 29) ^ x0;
    x0 += x1; x1 = rotl32(x1, 16) ^ x0;
    x0 += x1; x1 = rotl32(x1, 24) ^ x0;
    x0 += k1; x1 += k2 + 4u;
    x0 += x1; x1 = rotl32(x1, 13) ^ x0;
    x0 += x1; x1 = rotl32(x1, 15) ^ x0;
    x0 += x1; x1 = rotl32(x1, 26) ^ x0;
    x0 += x1; x1 = rotl32(x1,  6) ^ x0;
    x0 += k2; x1 += k0 + 5u;
    return TF2{x0, x1};
}

constexpr TF2 KB = tf2x32(0u, 42u, 0u, 0u);   // k_bern (foldlike split of key 42)

// ---------------- 4-elem/thread bitonic helpers (128 threads, e = 4*t2+c) ---
#define BSWAP(A, PA, KEEPMIN) ((KEEPMIN) ? umin((A),(PA)) : umax((A),(PA)))
#define NBAR_SORT() asm volatile("bar.sync 1, 128;" ::: "memory")
#define NBAR_MASK() asm volatile("bar.sync 2, 128;" ::: "memory")

#define CE(A, B, ASC) { uint32_t lo_ = umin(A,B), hi_ = umax(A,B);            \
                        A = (ASC) ? lo_ : hi_;  B = (ASC) ? hi_ : lo_; }

#define INTRA(D) { CE(v0, v2, D) CE(v1, v3, D) CE(v0, v1, D) CE(v2, v3, D) }

#define SSTAGE(J4, D) {                                                       \
    uint32_t p0_ = __shfl_xor_sync(0xFFFFFFFFu, v0, J4);                      \
    uint32_t p1_ = __shfl_xor_sync(0xFFFFFFFFu, v1, J4);                      \
    uint32_t p2_ = __shfl_xor_sync(0xFFFFFFFFu, v2, J4);                      \
    uint32_t p3_ = __shfl_xor_sync(0xFFFFFFFFu, v3, J4);                      \
    bool km_ = (D) == ((t2 & (J4)) == 0);                                     \
    v0 = BSWAP(v0, p0_, km_); v1 = BSWAP(v1, p1_, km_);                       \
    v2 = BSWAP(v2, p2_, km_); v3 = BSWAP(v3, p3_, km_); }

#define MSTAGE(J4, D) {                                                       \
    NBAR_SORT();                                                              \
    reinterpret_cast<uint4*>(sk)[t2] = make_uint4(v0, v1, v2, v3);            \
    NBAR_SORT();                                                              \
    uint4 pv_ = reinterpret_cast<uint4*>(sk)[t2 ^ (J4)];                      \
    bool km_ = (D) == ((t2 & (J4)) == 0);                                     \
    v0 = BSWAP(v0, pv_.x, km_); v1 = BSWAP(v1, pv_.y, km_);                   \
    v2 = BSWAP(v2, pv_.z, km_); v3 = BSWAP(v3, pv_.w, km_); }

// 5-step butterfly 32x32 bit-matrix transpose across lanes
#define TSTEP(V, K, M) {                                                      \
    uint32_t y_ = __shfl_xor_sync(0xFFFFFFFFu, V, K);                         \
    V = (lane & (K)) ? ((V & (M)) | ((y_ >> (K)) & ~(M)))                     \
                     : ((V & ~(M)) | ((y_ << (K)) & (M))); }

#define TRANSPOSE32(V) TSTEP(V, 16, 0xFFFF0000u) TSTEP(V, 8, 0xFF00FF00u)     \
                       TSTEP(V, 4,  0xF0F0F0F0u) TSTEP(V, 2, 0xCCCCCCCCu)     \
                       TSTEP(V, 1,  0xAAAAAAAAu)

// ---------------- fused persistent kernel -----------------------------------
__global__ __launch_bounds__(256, 4) void fused_kernel(
    const float* __restrict__ x, const float* __restrict__ pw,
    float* __restrict__ out) {
    __shared__ uint32_t sk[512];
    __shared__ float    s_xv[512];
    __shared__ uint32_t s_ti[64];
    __shared__ float    s_tv[64];
    __shared__ float    s_wx[32][17], s_wy[32][17];   // padded: conflict-free
    __shared__ uint32_t s_m[64][17];                  // staged sel words
    __shared__ unsigned s_tgt;

    const int t    = threadIdx.x;
    const int bid  = blockIdx.x;
    const int lane = t & 31;

    if (t < 128) {
        // ==== warps 0-3: mask for (ow = bid&15, i in [ib,ib+16)) ============
        const uint32_t ow = (uint32_t)bid & 15u;
        const uint32_t ib = ((uint32_t)bid >> 4) * 16u;
        const uint32_t w  = (uint32_t)t >> 5;          // 0..3

        // stage the 32o x 16i pw block (4KB), 128B-contiguous loads
        const float2* pwp = reinterpret_cast<const float2*>(pw);
#pragma unroll
        for (int q = 0; q < 4; ++q) {
            int idx = q * 128 + t;                     // 0..511
            int ol = idx >> 4, ii = idx & 15;
            float2 v = pwp[(ow * 32u + ol) * 512u + ib + ii];
            s_wx[ol][ii] = v.x;
            s_wy[ol][ii] = v.y;
        }
        NBAR_MASK();

        const uint32_t o = ow * 32u + lane;
        uint32_t iloc[4]; bool s[4];
#pragma unroll
        for (int k = 0; k < 4; ++k) {
            iloc[k] = 4u * w + k;
            uint32_t n = o * 512u + ib + iloc[k];
            TF2 r = tf2x32(KB.a, KB.b, 0u, n);         // 4 independent chains
            uint32_t bits = r.a ^ r.b;
            float u = __uint_as_float((bits >> 9) | 0x3F800000u) - 1.0f;
            float wx = s_wx[lane][iloc[k]], wy = s_wy[lane][iloc[k]];
            float tt = u * (1.0f + __expf(wx - wy));
            if (tt < 1.0f - 1e-5f)      s[k] = true;
            else if (tt > 1.0f + 1e-5f) s[k] = false;
            else {                                     // boundary: exact fp64
                double e = exp((double)wx - (double)wy);
                s[k] = ((double)u) * (1.0 + e) < 1.0;
            }
        }
#pragma unroll
        for (int k = 0; k < 4; ++k) {
            uint32_t word = __ballot_sync(0xFFFFFFFFu, s[k]);
            if (lane == 0) g_sel[(ib + iloc[k]) * 16u + ow] = word;
        }
    } else {
        // ==== warps 4-7: 128-thread bitonic sort of x-row bid ===============
        const int t2 = t - 128;                        // 0..127, e = 4*t2+c
        float4 xv = reinterpret_cast<const float4*>(x + bid * IN_DIM)[t2];
        reinterpret_cast<float4*>(s_xv)[t2] = xv;
        uint32_t v0 = ((__float_as_uint(xv.x) >> 7) << 9) | (uint32_t)(4*t2+0);
        uint32_t v1 = ((__float_as_uint(xv.y) >> 7) << 9) | (uint32_t)(4*t2+1);
        uint32_t v2 = ((__float_as_uint(xv.z) >> 7) << 9) | (uint32_t)(4*t2+2);
        uint32_t v3 = ((__float_as_uint(xv.w) >> 7) << 9) | (uint32_t)(4*t2+3);

        CE(v0, v1, true) CE(v2, v3, false)                          // k=2
        { bool d = ((t2 & 1) == 0); INTRA(d) }                      // k=4
        { bool d = ((t2 & 2) == 0); SSTAGE(1, d) INTRA(d) }         // k=8
        { bool d = ((t2 & 4) == 0); SSTAGE(2, d) SSTAGE(1, d) INTRA(d) }
        { bool d = ((t2 & 8) == 0); SSTAGE(4, d) SSTAGE(2, d) SSTAGE(1, d) INTRA(d) }
        { bool d = ((t2 & 16) == 0);
          SSTAGE(8, d) SSTAGE(4, d) SSTAGE(2, d) SSTAGE(1, d) INTRA(d) }
        { bool d = ((t2 & 32) == 0);
          SSTAGE(16, d) SSTAGE(8, d) SSTAGE(4, d) SSTAGE(2, d) SSTAGE(1, d) INTRA(d) }
        { bool d = ((t2 & 64) == 0);
          MSTAGE(32, d)
          SSTAGE(16, d) SSTAGE(8, d) SSTAGE(4, d) SSTAGE(2, d) SSTAGE(1, d) INTRA(d) }
        { const bool d = true;                                      // k=512
          MSTAGE(64, d) MSTAGE(32, d)
          SSTAGE(16, d) SSTAGE(8, d) SSTAGE(4, d) SSTAGE(2, d) SSTAGE(1, d) INTRA(d) }

        if (t2 < 16) {                 // sorted elems 0..63 -> smem top list
            uint32_t i0 = v0 & 511u, i1 = v1 & 511u,
                     i2 = v2 & 511u, i3 = v3 & 511u;
            s_ti[4*t2+0] = i0;  s_tv[4*t2+0] = s_xv[i0];
            s_ti[4*t2+1] = i1;  s_tv[4*t2+1] = s_xv[i1];
            s_ti[4*t2+2] = i2;  s_tv[4*t2+2] = s_xv[i2];
            s_ti[4*t2+3] = i3;  s_tv[4*t2+3] = s_xv[i3];
        }
    }

    // ======== grid barrier (all co-resident: 512 blocks <= 148*4) ===========
    __syncthreads();
    if (t == 0) {
        __threadfence();
        unsigned arr = atomicAdd(&g_bar, 1u);
        s_tgt = (arr / NBLK + 1u) * NBLK;
    }
    __syncthreads();
    if (t == 0) {
        unsigned tgt = s_tgt, v;
        for (;;) {
            asm volatile("ld.global.acquire.gpu.u32 %0, [%1];"
                         : "=r"(v) : "l"(&g_bar));
            if (v >= tgt) break;
            __nanosleep(64);
        }
    }
    __syncthreads();

    // ======== Phase C: staged gather for b = bid ============================
    // stage sel words for 64 candidates x 16 ow (64B-contiguous global loads)
#pragma unroll
    for (int q = 0; q < 4; ++q) {
        int idx = q * 256 + t;                         // 0..1023
        int j = idx >> 4, ow2 = idx & 15;
        s_m[j][ow2] = g_sel[s_ti[j] * 16u + ow2];
    }
    __syncthreads();

    {
        const uint32_t wrp = (uint32_t)t >> 5;        // 0..7
        const uint32_t ow0 = wrp, ow1 = wrp + 8u;
        float val = s_tv[lane];
        uint32_t m0 = s_m[lane][ow0];                 // conflict-free (pad 17)
        uint32_t m1 = s_m[lane][ow1];
        TRANSPOSE32(m0)
        TRANSPOSE32(m1)
        bool ok0 = (m0 != 0), ok1 = (m1 != 0);
        float r0 = __shfl_sync(0xFFFFFFFFu, val, ok0 ? (__ffs(m0) - 1) : 0);
        float r1 = __shfl_sync(0xFFFFFFFFu, val, ok1 ? (__ffs(m1) - 1) : 0);

        if (!__all_sync(0xFFFFFFFFu, ok0 && ok1)) {   // P ~ 2.6e-3 per warp
            float val2 = s_tv[32 + lane];
            uint32_t n0 = s_m[32 + lane][ow0];
            uint32_t n1 = s_m[32 + lane][ow1];
            TRANSPOSE32(n0)
            TRANSPOSE32(n1)
            float q0 = __shfl_sync(0xFFFFFFFFu, val2, n0 ? (__ffs(n0) - 1) : 0);
            float q1 = __shfl_sync(0xFFFFFFFFu, val2, n1 ? (__ffs(n1) - 1) : 0);
            if (!ok0 && n0) { r0 = q0; ok0 = true; }
            if (!ok1 && n1) { r1 = q1; ok1 = true; }

            if (!ok0 || !ok1) {                       // P ~ 1e-9: exact dense
                float b0 = INFINITY, b1 = INFINITY, ball = INFINITY;
                for (int i = 0; i < IN_DIM; ++i) {
                    float v = s_xv[i];
                    ball = fminf(ball, v);
                    if ((g_sel[i * 16u + ow0] >> lane) & 1u) b0 = fminf(b0, v);
                    if ((g_sel[i * 16u + ow1] >> lane) & 1u) b1 = fminf(b1, v);
                }
                if (!ok0) r0 = isinf(b0) ? ball + 1.0f : b0;
                if (!ok1) r1 = isinf(b1) ? ball + 1.0f : b1;
            }
        }

        out[bid * OUT_DIM + ow0 * 32u + lane] = r0;   // coalesced
        out[bid * OUT_DIM + ow1 * 32u + lane] = r1;
    }
}

// ---------------------------------------------------------------------------
extern "C" void kernel_launch(void* const* d_in, const int* in_sizes, int n_in,
                              void* d_out, int out_size) {
    const float* x  = (const float*)d_in[0];   // [512, 512]
    const float* pw = (const float*)d_in[1];   // [512, 512, 2]
    float* out      = (float*)d_out;           // [512, 512]

    fused_kernel<<<NBLK, 256>>>(x, pw, out);
}